// round 1
// baseline (speedup 1.0000x reference)
#include <cuda_runtime.h>
#include <cuda_bf16.h>

#define NB 8
#define NC 512
#define NM 64
#define NN 4096
#define EPSF 1e-6f
#define NSPLIT 8

// ---------------- scratch (device globals; no allocation) ----------------
__device__ float gQ[NB * NM * NN];            // [b,m,n]
__device__ float gK[NB * NM * NN];            // [b,m,n]
__device__ float gQnT[NB * NN * NM];          // [b,n,m] normalized Q
__device__ float gKnT[NB * NN * NM];          // [b,n,m] normalized K
__device__ float gV[NB * NC * NN];            // [b,c,n]
__device__ float gMatPart[NSPLIT * NB * NM * NC];
__device__ float gMat[NB * NM * NC];          // [b,m,c]
__device__ float gKsum[NB * NM];
__device__ float gVsum[NB * NC];
__device__ float gTailor[NB * NN];

// ---------------- 1x1 conv as GEMM: out[b,i,n] = sum_c W[i,c] x[b,c,n] + bias[i]
// 64x64 tile, BK=16, 256 threads, 4x4 microtile.
template <int SEL>
__global__ void conv_gemm_t(const float* __restrict__ W,
                            const float* __restrict__ bias,
                            const float* __restrict__ x, int I) {
    float* out = (SEL == 0) ? gQ : ((SEL == 1) ? gK : gV);
    __shared__ __align__(16) float Ws[16][64];  // [k][i]
    __shared__ __align__(16) float Xs[16][64];  // [k][n]
    int t = threadIdx.x;
    int tx = t & 15, ty = t >> 4;
    int bi = blockIdx.x << 6;
    int bn = blockIdx.y << 6;
    int b = blockIdx.z;
    const float* xb = x + (size_t)b * NC * NN;
    float acc[4][4] = {};
    int wrow = t >> 2, wk = (t & 3) << 2;   // W tile: 64 rows(i) x 16 k
    int xk = t >> 4, xn = (t & 15) << 2;    // X tile: 16 rows(k) x 64 n

    for (int k0 = 0; k0 < NC; k0 += 16) {
        float4 w4 = *(const float4*)&W[(size_t)(bi + wrow) * NC + k0 + wk];
        Ws[wk + 0][wrow] = w4.x; Ws[wk + 1][wrow] = w4.y;
        Ws[wk + 2][wrow] = w4.z; Ws[wk + 3][wrow] = w4.w;
        float4 x4 = *(const float4*)&xb[(size_t)(k0 + xk) * NN + bn + xn];
        *(float4*)&Xs[xk][xn] = x4;
        __syncthreads();
#pragma unroll
        for (int k = 0; k < 16; k++) {
            float a[4], bb[4];
#pragma unroll
            for (int i = 0; i < 4; i++) a[i] = Ws[k][ty + (i << 4)];
#pragma unroll
            for (int j = 0; j < 4; j++) bb[j] = Xs[k][tx + (j << 4)];
#pragma unroll
            for (int i = 0; i < 4; i++)
#pragma unroll
                for (int j = 0; j < 4; j++)
                    acc[i][j] = fmaf(a[i], bb[j], acc[i][j]);
        }
        __syncthreads();
    }
#pragma unroll
    for (int i = 0; i < 4; i++) {
        int ii = bi + ty + (i << 4);
        float bs = bias[ii];
        size_t base = ((size_t)b * I + ii) * NN + bn;
#pragma unroll
        for (int j = 0; j < 4; j++)
            out[base + tx + (j << 4)] = acc[i][j] + bs;
    }
}

// ---------------- L2-normalize Q,K over channel dim, write transposed [b,n,64]
__global__ void normalize_qk() {
    __shared__ float Qs[64][33];
    __shared__ float Ks[64][33];
    int t = threadIdx.x;
    int n0 = blockIdx.x << 5;  // 32 columns per block
    int b = blockIdx.y;
    int row = t >> 2, noff = (t & 3) << 3;  // 8 floats per thread
    size_t qbase = ((size_t)b * NM + row) * NN + n0 + noff;
    float4 a0 = *(const float4*)&gQ[qbase];
    float4 a1 = *(const float4*)&gQ[qbase + 4];
    Qs[row][noff + 0] = a0.x; Qs[row][noff + 1] = a0.y;
    Qs[row][noff + 2] = a0.z; Qs[row][noff + 3] = a0.w;
    Qs[row][noff + 4] = a1.x; Qs[row][noff + 5] = a1.y;
    Qs[row][noff + 6] = a1.z; Qs[row][noff + 7] = a1.w;
    float4 b0 = *(const float4*)&gK[qbase];
    float4 b1 = *(const float4*)&gK[qbase + 4];
    Ks[row][noff + 0] = b0.x; Ks[row][noff + 1] = b0.y;
    Ks[row][noff + 2] = b0.z; Ks[row][noff + 3] = b0.w;
    Ks[row][noff + 4] = b1.x; Ks[row][noff + 5] = b1.y;
    Ks[row][noff + 6] = b1.z; Ks[row][noff + 7] = b1.w;
    __syncthreads();
    int w = t >> 5, lane = t & 31;
#pragma unroll
    for (int j = 0; j < 4; j++) {
        int col = (w << 2) + j;
        float q1 = Qs[lane][col], q2 = Qs[lane + 32][col];
        float k1 = Ks[lane][col], k2 = Ks[lane + 32][col];
        float sq = q1 * q1 + q2 * q2;
        float sk = k1 * k1 + k2 * k2;
#pragma unroll
        for (int o = 16; o; o >>= 1) {
            sq += __shfl_xor_sync(0xFFFFFFFFu, sq, o);
            sk += __shfl_xor_sync(0xFFFFFFFFu, sk, o);
        }
        float rq = rsqrtf(sq), rk = rsqrtf(sk);
        size_t ob = ((size_t)b * NN + n0 + col) * NM;
        gQnT[ob + lane] = q1 * rq;
        gQnT[ob + lane + 32] = q2 * rq;
        gKnT[ob + lane] = k1 * rk;
        gKnT[ob + lane + 32] = k2 * rk;
    }
}

// ---------------- Ksum[b,m] = sum_n Kn[b,m,n]
__global__ void ksum_kernel() {
    int b = blockIdx.x;
    int t = threadIdx.x;
    int m = t & 63, part = t >> 6;  // 4 partial streams
    float s = 0.f;
    for (int n = part; n < NN; n += 4)
        s += gKnT[((size_t)b * NN + n) * NM + m];
    __shared__ float red[4][64];
    red[part][m] = s;
    __syncthreads();
    if (part == 0)
        gKsum[b * NM + m] = red[0][m] + red[1][m] + red[2][m] + red[3][m];
}

// ---------------- Vsum[b,c] = sum_n V[b,c,n]
__global__ void vsum_kernel() {
    int c = blockIdx.x, b = blockIdx.y;
    int t = threadIdx.x;
    const float* vp = &gV[((size_t)b * NC + c) * NN];
    float s = 0.f;
    for (int n = t; n < NN; n += 256) s += vp[n];
    __shared__ float red[256];
    red[t] = s;
    __syncthreads();
    for (int o = 128; o; o >>= 1) {
        if (t < o) red[t] += red[t + o];
        __syncthreads();
    }
    if (t == 0) gVsum[b * NC + c] = red[0];
}

// ---------------- matrix[b,m,c] = sum_n Kn[b,m,n] V[b,c,n] (split over n, deterministic)
__global__ void kv_matrix() {
    __shared__ __align__(16) float As[16][64];  // [n_k][m]
    __shared__ float Vs[64][17];                // [c][n_k] padded
    int t = threadIdx.x;
    int tx = t & 15, ty = t >> 4;  // c = bc+tx+j*16, m = ty+i*16
    int bc = blockIdx.x << 6;
    int split = blockIdx.y;
    int n0 = split << 9;  // 512 n per split
    int b = blockIdx.z;
    float acc[4][4] = {};
    int ar = t >> 4, am = (t & 15) << 2;
    int vr = t >> 2, vk = (t & 3) << 2;

    for (int nk = 0; nk < 512; nk += 16) {
        int nbase = n0 + nk;
        float4 a4 = *(const float4*)&gKnT[((size_t)b * NN + nbase + ar) * NM + am];
        *(float4*)&As[ar][am] = a4;
        float4 v4 = *(const float4*)&gV[((size_t)b * NC + bc + vr) * NN + nbase + vk];
        Vs[vr][vk + 0] = v4.x; Vs[vr][vk + 1] = v4.y;
        Vs[vr][vk + 2] = v4.z; Vs[vr][vk + 3] = v4.w;
        __syncthreads();
#pragma unroll
        for (int k = 0; k < 16; k++) {
            float a[4], vv[4];
#pragma unroll
            for (int i = 0; i < 4; i++) a[i] = As[k][ty + (i << 4)];
#pragma unroll
            for (int j = 0; j < 4; j++) vv[j] = Vs[tx + (j << 4)][k];
#pragma unroll
            for (int i = 0; i < 4; i++)
#pragma unroll
                for (int j = 0; j < 4; j++)
                    acc[i][j] = fmaf(a[i], vv[j], acc[i][j]);
        }
        __syncthreads();
    }
    size_t pbase = ((size_t)split * NB + b) * NM * NC;
#pragma unroll
    for (int i = 0; i < 4; i++)
#pragma unroll
        for (int j = 0; j < 4; j++)
            gMatPart[pbase + (size_t)(ty + (i << 4)) * NC + bc + tx + (j << 4)] = acc[i][j];
}

__global__ void reduce_mat() {
    int i = blockIdx.x * 256 + threadIdx.x;
    if (i < NB * NM * NC) {
        float s = 0.f;
#pragma unroll
        for (int sp = 0; sp < NSPLIT; sp++)
            s += gMatPart[(size_t)sp * NB * NM * NC + i];
        gMat[i] = s;
    }
}

// ---------------- tailor[b,n] = 1/(N + Qn[b,n,:].(Ksum+eps))
__global__ void tailor_kernel() {
    __shared__ float ks[64];
    int t = threadIdx.x;
    int b = blockIdx.y;
    if (t < 64) ks[t] = gKsum[b * NM + t] + EPSF;
    __syncthreads();
    int w = t >> 5, lane = t & 31;
    int n = (blockIdx.x << 3) + w;
    const float* q = &gQnT[((size_t)b * NN + n) * NM];
    float s = q[lane] * ks[lane] + q[lane + 32] * ks[lane + 32];
#pragma unroll
    for (int o = 16; o; o >>= 1) s += __shfl_xor_sync(0xFFFFFFFFu, s, o);
    if (lane == 0) gTailor[b * NN + n] = 1.0f / ((float)NN + s);
}

// ---------------- out[b,c,n] = x + gamma*(Vsum[c] + sum_m Qn[n,m] matrix[m,c]) * tailor[n]
__global__ void final_kernel(const float* __restrict__ x,
                             const float* __restrict__ gamma,
                             float* __restrict__ out) {
    __shared__ float Qs[64][65];                // [n][m] padded
    __shared__ __align__(16) float Ms[64][64];  // [m][c]
    int t = threadIdx.x;
    int tx = t & 15, ty = t >> 4;  // n = bn+tx+j*16, c = bc+ty+i*16
    int bc = blockIdx.x << 6;
    int bn = blockIdx.y << 6;
    int b = blockIdx.z;

    int qr = t >> 2, qc0 = (t & 3) << 4;
    size_t qb = ((size_t)b * NN + bn + qr) * NM + qc0;
    size_t mb = ((size_t)b * NM + qr) * NC + bc + qc0;
#pragma unroll
    for (int q = 0; q < 4; q++) {
        float4 v = *(const float4*)&gQnT[qb + (q << 2)];
        Qs[qr][qc0 + (q << 2) + 0] = v.x; Qs[qr][qc0 + (q << 2) + 1] = v.y;
        Qs[qr][qc0 + (q << 2) + 2] = v.z; Qs[qr][qc0 + (q << 2) + 3] = v.w;
        *(float4*)&Ms[qr][qc0 + (q << 2)] = *(const float4*)&gMat[mb + (q << 2)];
    }
    __syncthreads();

    float acc[4][4] = {};
#pragma unroll
    for (int m = 0; m < 64; m++) {
        float qv[4], mv[4];
#pragma unroll
        for (int j = 0; j < 4; j++) qv[j] = Qs[tx + (j << 4)][m];
#pragma unroll
        for (int i = 0; i < 4; i++) mv[i] = Ms[m][ty + (i << 4)];
#pragma unroll
        for (int i = 0; i < 4; i++)
#pragma unroll
            for (int j = 0; j < 4; j++)
                acc[i][j] = fmaf(mv[i], qv[j], acc[i][j]);
    }

    float g = gamma[0];
    float tl[4];
#pragma unroll
    for (int j = 0; j < 4; j++) tl[j] = gTailor[b * NN + bn + tx + (j << 4)];
#pragma unroll
    for (int i = 0; i < 4; i++) {
        int c = bc + ty + (i << 4);
        float vs = gVsum[b * NC + c];
        size_t base = ((size_t)b * NC + c) * NN + bn;
#pragma unroll
        for (int j = 0; j < 4; j++) {
            size_t idx = base + tx + (j << 4);
            out[idx] = x[idx] + g * (vs + acc[i][j]) * tl[j];
        }
    }
}

extern "C" void kernel_launch(void* const* d_in, const int* in_sizes, int n_in,
                              void* d_out, int out_size) {
    const float* x = (const float*)d_in[0];
    const float* Wq = (const float*)d_in[1];
    const float* bq = (const float*)d_in[2];
    const float* Wk = (const float*)d_in[3];
    const float* bk = (const float*)d_in[4];
    const float* Wv = (const float*)d_in[5];
    const float* bv = (const float*)d_in[6];
    const float* gamma = (const float*)d_in[7];
    float* out = (float*)d_out;
    (void)in_sizes; (void)n_in; (void)out_size;

    dim3 blk(256);
    conv_gemm_t<0><<<dim3(1, 64, NB), blk>>>(Wq, bq, x, NM);
    conv_gemm_t<1><<<dim3(1, 64, NB), blk>>>(Wk, bk, x, NM);
    conv_gemm_t<2><<<dim3(8, 64, NB), blk>>>(Wv, bv, x, NC);
    normalize_qk<<<dim3(128, NB), blk>>>();
    ksum_kernel<<<NB, blk>>>();
    vsum_kernel<<<dim3(NC, NB), blk>>>();
    kv_matrix<<<dim3(8, NSPLIT, NB), blk>>>();
    reduce_mat<<<(NB * NM * NC + 255) / 256, blk>>>();
    tailor_kernel<<<dim3(NN / 8, NB), blk>>>();
    final_kernel<<<dim3(8, 64, NB), blk>>>(x, gamma, out);
}

// round 4
// speedup vs baseline: 4.6758x; 4.6758x over previous
#include <cuda_runtime.h>
#include <cuda_bf16.h>
#include <cstdint>

#define NB 8
#define NC 512
#define NM 64
#define NN 4096
#define NI 640          // fused QKV output channels
#define EPSF 1e-6f
#define NSPLIT 8

// ---------------------------------------------------------------- scratch
__device__ __align__(16) __nv_bfloat16 gWh[NI * NC];             // fused weights [640,512]
__device__ float gBiasF[NI];
__device__ __align__(16) __nv_bfloat16 gXh[(size_t)NB * NN * NC];   // x transposed [b,n,c]
__device__ __align__(16) __nv_bfloat16 gQh[(size_t)NB * NM * NN];   // [b,m,n]
__device__ __align__(16) __nv_bfloat16 gKh[(size_t)NB * NM * NN];   // [b,m,n]
__device__ __align__(16) __nv_bfloat16 gVh[(size_t)NB * NC * NN];   // [b,c,n]
__device__ __align__(16) __nv_bfloat16 gQnTh[(size_t)NB * NN * NM]; // [b,n,m]
__device__ __align__(16) __nv_bfloat16 gKnH[(size_t)NB * NM * NN];  // [b,m,n]
__device__ __align__(16) float gMatPartT[(size_t)NSPLIT * NB * NC * NM]; // [sp,b,c,m]
__device__ __align__(16) __nv_bfloat16 gMatTh[(size_t)NB * NC * NM];     // [b,c,m]
__device__ float gKsum[NB * NM];
__device__ float gVsum[NB * NC];
__device__ float gTailor[NB * NN];

// ---------------------------------------------------------------- helpers
__device__ __forceinline__ uint32_t smem_to_u32(const void* p) {
    uint32_t a;
    asm("{ .reg .u64 t; cvta.to.shared.u64 t, %1; cvt.u32.u64 %0, t; }" : "=r"(a) : "l"(p));
    return a;
}
__device__ __forceinline__ void ldsm4(uint32_t& r0, uint32_t& r1, uint32_t& r2,
                                      uint32_t& r3, uint32_t addr) {
    asm volatile("ldmatrix.sync.aligned.m8n8.x4.shared.b16 {%0,%1,%2,%3}, [%4];"
                 : "=r"(r0), "=r"(r1), "=r"(r2), "=r"(r3) : "r"(addr));
}
__device__ __forceinline__ void mma_bf16(float* d, const uint32_t* a, const uint32_t* b) {
    asm volatile(
        "mma.sync.aligned.m16n8k16.row.col.f32.bf16.bf16.f32 "
        "{%0,%1,%2,%3}, {%4,%5,%6,%7}, {%8,%9}, {%0,%1,%2,%3};"
        : "+f"(d[0]), "+f"(d[1]), "+f"(d[2]), "+f"(d[3])
        : "r"(a[0]), "r"(a[1]), "r"(a[2]), "r"(a[3]), "r"(b[0]), "r"(b[1]));
}

#define PITCH 72   // bf16 elements per smem row (144 B) — conflict-free ldmatrix

// ---------------------------------------------------------------- tiny prep
__global__ void pack_weights(const float* __restrict__ Wq, const float* __restrict__ bq,
                             const float* __restrict__ Wk, const float* __restrict__ bk,
                             const float* __restrict__ Wv, const float* __restrict__ bv) {
    int i = blockIdx.x, t = threadIdx.x;
    const float* src; float bs;
    if (i < 64) { src = Wq + (size_t)i * NC; bs = bq[i]; }
    else if (i < 128) { src = Wk + (size_t)(i - 64) * NC; bs = bk[i - 64]; }
    else { src = Wv + (size_t)(i - 128) * NC; bs = bv[i - 128]; }
    __nv_bfloat16* dst = gWh + (size_t)i * NC;
    for (int c = t; c < NC; c += 256) dst[c] = __float2bfloat16(src[c]);
    if (t == 0) gBiasF[i] = bs;
}

__global__ void transpose_x(const float* __restrict__ x) {
    __shared__ float tile[32][33];
    int tx = threadIdx.x, ty = threadIdx.y;
    int n0 = blockIdx.x << 5, c0 = blockIdx.y << 5, b = blockIdx.z;
#pragma unroll
    for (int j = 0; j < 4; j++)
        tile[ty + 8 * j][tx] = x[((size_t)b * NC + c0 + ty + 8 * j) * NN + n0 + tx];
    __syncthreads();
#pragma unroll
    for (int j = 0; j < 4; j++)
        gXh[((size_t)b * NN + n0 + ty + 8 * j) * NC + c0 + tx] =
            __float2bfloat16(tile[tx][ty + 8 * j]);
}

// ---------------------------------------------------------------- fused QKV conv
// D[i,n] = sum_c Wh[i,c] * XT[n,c].  CTA tile 128x128, K=512 in 8 chunks of 64.
__global__ void conv_mma() {
    __shared__ __align__(16) __nv_bfloat16 As[128][PITCH];
    __shared__ __align__(16) __nv_bfloat16 Bs[128][PITCH];
    int t = threadIdx.x, wid = t >> 5, lane = t & 31;
    int bi = blockIdx.x << 7, bn = blockIdx.y << 7, b = blockIdx.z;
    int wm = wid & 1, wn = wid >> 1;
    const __nv_bfloat16* Ag = gWh + (size_t)bi * NC;
    const __nv_bfloat16* Bg = gXh + ((size_t)b * NN + bn) * NC;
    float acc[4][4][4] = {};
    uint32_t aBase = smem_to_u32(As), bBase = smem_to_u32(Bs);
    int g = lane >> 3, lr = lane & 7;
    uint32_t aAddr = aBase + (uint32_t)(((wm * 64 + (g & 1) * 8 + lr) * PITCH + (g >> 1) * 8) * 2);
    uint32_t bAddr = bBase + (uint32_t)(((wn * 32 + (g >> 1) * 8 + lr) * PITCH + (g & 1) * 8) * 2);
    int lrow = t >> 1, lcol = (t & 1) * 32;

    for (int ch = 0; ch < 8; ch++) {
        int k0 = ch * 64;
        const uint4* sa = (const uint4*)(Ag + (size_t)lrow * NC + k0 + lcol);
        uint4* da = (uint4*)(&As[lrow][lcol]);
        da[0] = sa[0]; da[1] = sa[1]; da[2] = sa[2]; da[3] = sa[3];
        const uint4* sb = (const uint4*)(Bg + (size_t)lrow * NC + k0 + lcol);
        uint4* db = (uint4*)(&Bs[lrow][lcol]);
        db[0] = sb[0]; db[1] = sb[1]; db[2] = sb[2]; db[3] = sb[3];
        __syncthreads();
#pragma unroll
        for (int ks = 0; ks < 4; ks++) {
            int kk = ks * 32;  // byte offset (16 bf16)
            uint32_t a[4][4], bf[4][2];
#pragma unroll
            for (int mi = 0; mi < 4; mi++)
                ldsm4(a[mi][0], a[mi][1], a[mi][2], a[mi][3],
                      aAddr + mi * (16 * PITCH * 2) + kk);
#pragma unroll
            for (int p = 0; p < 2; p++) {
                uint32_t r0, r1, r2, r3;
                ldsm4(r0, r1, r2, r3, bAddr + p * (16 * PITCH * 2) + kk);
                bf[2 * p][0] = r0; bf[2 * p][1] = r1;
                bf[2 * p + 1][0] = r2; bf[2 * p + 1][1] = r3;
            }
#pragma unroll
            for (int mi = 0; mi < 4; mi++)
#pragma unroll
                for (int ni = 0; ni < 4; ni++)
                    mma_bf16(acc[mi][ni], a[mi], bf[ni]);
        }
        __syncthreads();
    }

    int r = lane >> 2, cp = (lane & 3) << 1;
#pragma unroll
    for (int mi = 0; mi < 4; mi++) {
#pragma unroll
        for (int half = 0; half < 2; half++) {
            int ig = bi + wm * 64 + mi * 16 + half * 8 + r;
            float bias = gBiasF[ig];
            __nv_bfloat16* dst;
            if (ig < 64)       dst = gQh + ((size_t)b * NM + ig) * NN;
            else if (ig < 128) dst = gKh + ((size_t)b * NM + ig - 64) * NN;
            else               dst = gVh + ((size_t)b * NC + ig - 128) * NN;
            dst += bn + wn * 32;
#pragma unroll
            for (int ni = 0; ni < 4; ni++) {
                __nv_bfloat162 v = __floats2bfloat162_rn(acc[mi][ni][half * 2] + bias,
                                                         acc[mi][ni][half * 2 + 1] + bias);
                *(uint32_t*)&dst[ni * 8 + cp] = *(uint32_t*)&v;
            }
        }
    }
}

// ---------------------------------------------------------------- normalize Q,K
__global__ void normalize_qk() {
    __shared__ float Qs[64][33];
    __shared__ float Ks[64][33];
    int t = threadIdx.x;
    int n0 = blockIdx.x << 5;
    int b = blockIdx.y;
    int row = t >> 2, off = (t & 3) << 3;
    uint4 qv = *(const uint4*)(gQh + ((size_t)b * NM + row) * NN + n0 + off);
    uint4 kv = *(const uint4*)(gKh + ((size_t)b * NM + row) * NN + n0 + off);
    const __nv_bfloat162* qp = (const __nv_bfloat162*)&qv;
    const __nv_bfloat162* kp = (const __nv_bfloat162*)&kv;
#pragma unroll
    for (int j = 0; j < 4; j++) {
        float2 fq = __bfloat1622float2(qp[j]);
        float2 fk = __bfloat1622float2(kp[j]);
        Qs[row][off + 2 * j] = fq.x; Qs[row][off + 2 * j + 1] = fq.y;
        Ks[row][off + 2 * j] = fk.x; Ks[row][off + 2 * j + 1] = fk.y;
    }
    __syncthreads();
    int w = t >> 5, lane = t & 31;
#pragma unroll
    for (int j = 0; j < 4; j++) {
        int col = (w << 2) + j;
        float q1 = Qs[lane][col], q2 = Qs[lane + 32][col];
        float k1 = Ks[lane][col], k2 = Ks[lane + 32][col];
        float sq = q1 * q1 + q2 * q2;
        float sk = k1 * k1 + k2 * k2;
#pragma unroll
        for (int o = 16; o; o >>= 1) {
            sq += __shfl_xor_sync(0xFFFFFFFFu, sq, o);
            sk += __shfl_xor_sync(0xFFFFFFFFu, sk, o);
        }
        float rq = rsqrtf(sq + 1e-30f), rk = rsqrtf(sk + 1e-30f);
        __nv_bfloat16* qd = gQnTh + ((size_t)b * NN + n0 + col) * NM;
        qd[lane] = __float2bfloat16(q1 * rq);
        qd[lane + 32] = __float2bfloat16(q2 * rq);
        Ks[lane][col] = k1 * rk;
        Ks[lane + 32][col] = k2 * rk;
    }
    __syncthreads();
    __nv_bfloat162 o2[4];
#pragma unroll
    for (int j = 0; j < 4; j++)
        o2[j] = __floats2bfloat162_rn(Ks[row][off + 2 * j], Ks[row][off + 2 * j + 1]);
    *(uint4*)(gKnH + ((size_t)b * NM + row) * NN + n0 + off) = *(uint4*)o2;
}

// ---------------------------------------------------------------- row sums
__global__ void ksum_kernel() {
    int m = blockIdx.x, b = blockIdx.y, t = threadIdx.x;
    const __nv_bfloat162* p = (const __nv_bfloat162*)(gKnH + ((size_t)b * NM + m) * NN);
    float s = 0.f;
    for (int i = t; i < NN / 2; i += 256) {
        float2 f = __bfloat1622float2(p[i]);
        s += f.x + f.y;
    }
#pragma unroll
    for (int o = 16; o; o >>= 1) s += __shfl_xor_sync(0xFFFFFFFFu, s, o);
    __shared__ float red[8];
    if ((t & 31) == 0) red[t >> 5] = s;
    __syncthreads();
    if (t == 0) {
        float tot = 0.f;
#pragma unroll
        for (int i = 0; i < 8; i++) tot += red[i];
        gKsum[b * NM + m] = tot;
    }
}

__global__ void vsum_kernel() {
    int c = blockIdx.x, b = blockIdx.y, t = threadIdx.x;
    const __nv_bfloat162* p = (const __nv_bfloat162*)(gVh + ((size_t)b * NC + c) * NN);
    float s = 0.f;
    for (int i = t; i < NN / 2; i += 256) {
        float2 f = __bfloat1622float2(p[i]);
        s += f.x + f.y;
    }
#pragma unroll
    for (int o = 16; o; o >>= 1) s += __shfl_xor_sync(0xFFFFFFFFu, s, o);
    __shared__ float red[8];
    if ((t & 31) == 0) red[t >> 5] = s;
    __syncthreads();
    if (t == 0) {
        float tot = 0.f;
#pragma unroll
        for (int i = 0; i < 8; i++) tot += red[i];
        gVsum[b * NC + c] = tot;
    }
}

// ---------------------------------------------------------------- KV contraction
// D[c,m] = sum_n V[c,n] * Kn[m,n].  CTA tile 128(c) x 64(m), K=512 per split.
__global__ void kv_mma() {
    __shared__ __align__(16) __nv_bfloat16 As[128][PITCH];
    __shared__ __align__(16) __nv_bfloat16 Bs[64][PITCH];
    int t = threadIdx.x, wid = t >> 5, lane = t & 31;
    int bc = blockIdx.x << 7, split = blockIdx.y, b = blockIdx.z;
    int wm = wid & 3, wn = wid >> 2;
    const __nv_bfloat16* Ag = gVh + ((size_t)b * NC + bc) * NN + split * 512;
    const __nv_bfloat16* Bg = gKnH + (size_t)b * NM * NN + split * 512;
    float acc[2][4][4] = {};
    uint32_t aBase = smem_to_u32(As), bBase = smem_to_u32(Bs);
    int g = lane >> 3, lr = lane & 7;
    uint32_t aAddr = aBase + (uint32_t)(((wm * 32 + (g & 1) * 8 + lr) * PITCH + (g >> 1) * 8) * 2);
    uint32_t bAddr = bBase + (uint32_t)(((wn * 32 + (g >> 1) * 8 + lr) * PITCH + (g & 1) * 8) * 2);
    int arow = t >> 1, acol = (t & 1) * 32;
    int brow = t >> 2, bcol = (t & 3) * 16;

    for (int ch = 0; ch < 8; ch++) {
        int k0 = ch * 64;
        const uint4* sa = (const uint4*)(Ag + (size_t)arow * NN + k0 + acol);
        uint4* da = (uint4*)(&As[arow][acol]);
        da[0] = sa[0]; da[1] = sa[1]; da[2] = sa[2]; da[3] = sa[3];
        const uint4* sb = (const uint4*)(Bg + (size_t)brow * NN + k0 + bcol);
        uint4* db = (uint4*)(&Bs[brow][bcol]);
        db[0] = sb[0]; db[1] = sb[1];
        __syncthreads();
#pragma unroll
        for (int ks = 0; ks < 4; ks++) {
            int kk = ks * 32;
            uint32_t a[2][4], bf[4][2];
#pragma unroll
            for (int mi = 0; mi < 2; mi++)
                ldsm4(a[mi][0], a[mi][1], a[mi][2], a[mi][3],
                      aAddr + mi * (16 * PITCH * 2) + kk);
#pragma unroll
            for (int p = 0; p < 2; p++) {
                uint32_t r0, r1, r2, r3;
                ldsm4(r0, r1, r2, r3, bAddr + p * (16 * PITCH * 2) + kk);
                bf[2 * p][0] = r0; bf[2 * p][1] = r1;
                bf[2 * p + 1][0] = r2; bf[2 * p + 1][1] = r3;
            }
#pragma unroll
            for (int mi = 0; mi < 2; mi++)
#pragma unroll
                for (int ni = 0; ni < 4; ni++)
                    mma_bf16(acc[mi][ni], a[mi], bf[ni]);
        }
        __syncthreads();
    }

    int r = lane >> 2, cp = (lane & 3) << 1;
#pragma unroll
    for (int mi = 0; mi < 2; mi++) {
#pragma unroll
        for (int half = 0; half < 2; half++) {
            int c = bc + wm * 32 + mi * 16 + half * 8 + r;
            float* dst = gMatPartT + (((size_t)split * NB + b) * NC + c) * NM + wn * 32;
#pragma unroll
            for (int ni = 0; ni < 4; ni++) {
                float2 v = make_float2(acc[mi][ni][half * 2], acc[mi][ni][half * 2 + 1]);
                *(float2*)&dst[ni * 8 + cp] = v;
            }
        }
    }
}

__global__ void reduce_matT() {
    int idx = blockIdx.x * 256 + threadIdx.x;
    float s = 0.f;
#pragma unroll
    for (int sp = 0; sp < NSPLIT; sp++)
        s += gMatPartT[(size_t)sp * (NB * NC * NM) + idx];
    gMatTh[idx] = __float2bfloat16(s);
}

// ---------------------------------------------------------------- tailor
__global__ void tailor_kernel() {
    __shared__ float ks[64];
    int t = threadIdx.x, b = blockIdx.y;
    if (t < 64) ks[t] = gKsum[b * NM + t] + EPSF;
    __syncthreads();
    int w = t >> 5, lane = t & 31;
    int n = (blockIdx.x << 3) + w;
    const __nv_bfloat162* q = (const __nv_bfloat162*)(gQnTh + ((size_t)b * NN + n) * NM);
    float2 f = __bfloat1622float2(q[lane]);
    float s = f.x * ks[2 * lane] + f.y * ks[2 * lane + 1];
#pragma unroll
    for (int o = 16; o; o >>= 1) s += __shfl_xor_sync(0xFFFFFFFFu, s, o);
    if (lane == 0) gTailor[b * NN + n] = 1.0f / ((float)NN + s);
}

// ---------------------------------------------------------------- final GEMM + epilogue
// D[c,n] = sum_m matT[c,m] * Qn[n,m].  CTA tile 128x128, K=64 single chunk.
__global__ void final_mma(const float* __restrict__ x, const float* __restrict__ gamma,
                          float* __restrict__ out) {
    __shared__ __align__(16) __nv_bfloat16 As[128][PITCH];
    __shared__ __align__(16) __nv_bfloat16 Bs[128][PITCH];
    int t = threadIdx.x, wid = t >> 5, lane = t & 31;
    int bc = blockIdx.x << 7, bn = blockIdx.y << 7, b = blockIdx.z;
    int wm = wid & 1, wn = wid >> 1;
    const __nv_bfloat16* Ag = gMatTh + ((size_t)b * NC + bc) * NM;
    const __nv_bfloat16* Bg = gQnTh + ((size_t)b * NN + bn) * NM;
    float acc[4][4][4] = {};
    uint32_t aBase = smem_to_u32(As), bBase = smem_to_u32(Bs);
    int g = lane >> 3, lr = lane & 7;
    uint32_t aAddr = aBase + (uint32_t)(((wm * 64 + (g & 1) * 8 + lr) * PITCH + (g >> 1) * 8) * 2);
    uint32_t bAddr = bBase + (uint32_t)(((wn * 32 + (g >> 1) * 8 + lr) * PITCH + (g & 1) * 8) * 2);
    {
        // each row is 64 bf16 = 8 uint4; 2 threads per row -> 4 uint4 per thread
        int row = t >> 1, col = (t & 1) * 32;
        const uint4* sa = (const uint4*)(Ag + (size_t)row * NM + col);
        uint4* da = (uint4*)(&As[row][col]);
        da[0] = sa[0]; da[1] = sa[1]; da[2] = sa[2]; da[3] = sa[3];
        const uint4* sb = (const uint4*)(Bg + (size_t)row * NM + col);
        uint4* db = (uint4*)(&Bs[row][col]);
        db[0] = sb[0]; db[1] = sb[1]; db[2] = sb[2]; db[3] = sb[3];
    }
    __syncthreads();
#pragma unroll
    for (int ks = 0; ks < 4; ks++) {
        int kk = ks * 32;
        uint32_t a[4][4], bf[4][2];
#pragma unroll
        for (int mi = 0; mi < 4; mi++)
            ldsm4(a[mi][0], a[mi][1], a[mi][2], a[mi][3],
                  aAddr + mi * (16 * PITCH * 2) + kk);
#pragma unroll
        for (int p = 0; p < 2; p++) {
            uint32_t r0, r1, r2, r3;
            ldsm4(r0, r1, r2, r3, bAddr + p * (16 * PITCH * 2) + kk);
            bf[2 * p][0] = r0; bf[2 * p][1] = r1;
            bf[2 * p + 1][0] = r2; bf[2 * p + 1][1] = r3;
        }
#pragma unroll
        for (int mi = 0; mi < 4; mi++)
#pragma unroll
            for (int ni = 0; ni < 4; ni++)
                mma_bf16(acc[mi][ni], a[mi], bf[ni]);
    }

    int r = lane >> 2, cp = (lane & 3) << 1;
    float gm = gamma[0];
#pragma unroll
    for (int mi = 0; mi < 4; mi++) {
#pragma unroll
        for (int half = 0; half < 2; half++) {
            int c = bc + wm * 64 + mi * 16 + half * 8 + r;
            float vs = gVsum[b * NC + c];
            const float* xr = x + ((size_t)b * NC + c) * NN + bn + wn * 32;
            float* orow = out + ((size_t)b * NC + c) * NN + bn + wn * 32;
            const float* tr = gTailor + (size_t)b * NN + bn + wn * 32;
#pragma unroll
            for (int ni = 0; ni < 4; ni++) {
                int n = ni * 8 + cp;
                float2 xv = *(const float2*)&xr[n];
                float2 tv = *(const float2*)&tr[n];
                float2 ov;
                ov.x = xv.x + gm * (vs + acc[mi][ni][half * 2]) * tv.x;
                ov.y = xv.y + gm * (vs + acc[mi][ni][half * 2 + 1]) * tv.y;
                *(float2*)&orow[n] = ov;
            }
        }
    }
}

// ---------------------------------------------------------------- launch
extern "C" void kernel_launch(void* const* d_in, const int* in_sizes, int n_in,
                              void* d_out, int out_size) {
    const float* x = (const float*)d_in[0];
    const float* Wq = (const float*)d_in[1];
    const float* bq = (const float*)d_in[2];
    const float* Wk = (const float*)d_in[3];
    const float* bk = (const float*)d_in[4];
    const float* Wv = (const float*)d_in[5];
    const float* bv = (const float*)d_in[6];
    const float* gamma = (const float*)d_in[7];
    float* out = (float*)d_out;
    (void)in_sizes; (void)n_in; (void)out_size;

    pack_weights<<<NI, 256>>>(Wq, bq, Wk, bk, Wv, bv);
    transpose_x<<<dim3(NN / 32, NC / 32, NB), dim3(32, 8)>>>(x);
    conv_mma<<<dim3(NI / 128, NN / 128, NB), 256>>>();
    normalize_qk<<<dim3(NN / 32, NB), 256>>>();
    ksum_kernel<<<dim3(NM, NB), 256>>>();
    vsum_kernel<<<dim3(NC, NB), 256>>>();
    kv_mma<<<dim3(NC / 128, NSPLIT, NB), 256>>>();
    reduce_matT<<<(NB * NC * NM) / 256, 256>>>();
    tailor_kernel<<<dim3(NN / 8, NB), 256>>>();
    final_mma<<<dim3(NC / 128, NN / 128, NB), 256>>>(x, gamma, out);
}

// round 5
// speedup vs baseline: 5.1576x; 1.1030x over previous
#include <cuda_runtime.h>
#include <cuda_bf16.h>
#include <cuda_fp8.h>
#include <cstdint>

#define NB 8
#define NC 512
#define NM 64
#define NN 4096
#define NI 640
#define EPSF 1e-6f
#define NSPLIT 8

// ---------------------------------------------------------------- scratch
__device__ __align__(16) unsigned char gW8[NI * NC];                 // fp8 weights x64
__device__ float gBiasF[NI];
__device__ __align__(16) unsigned char gX8[(size_t)NB * NN * NC];    // fp8 x, [b,n,c]
__device__ __align__(16) __nv_bfloat16 gQh[(size_t)NB * NM * NN];    // [b,m,n]
__device__ __align__(16) __nv_bfloat16 gKh[(size_t)NB * NM * NN];    // [b,m,n]
__device__ __align__(16) __nv_bfloat16 gVh[(size_t)NB * NC * NN];    // [b,c,n]
__device__ __align__(16) __nv_bfloat16 gQnTh[(size_t)NB * NN * NM];  // [b,n,m]
__device__ __align__(16) __nv_bfloat16 gKnH[(size_t)NB * NM * NN];   // [b,m,n]
__device__ __align__(16) float gMatPartT[(size_t)NSPLIT * NB * NC * NM];
__device__ __align__(16) __nv_bfloat16 gMatTh[(size_t)NB * NC * NM]; // [b,c,m]
__device__ float gVsumP[(size_t)32 * NB * NC];   // [nblk,b,c]
__device__ float gKsumP[(size_t)128 * NB * NM];  // [nblk,b,m]
__device__ float gKsum[NB * NM];
__device__ float gVsum[NB * NC];

// ---------------------------------------------------------------- helpers
__device__ __forceinline__ uint32_t smem_to_u32(const void* p) {
    uint32_t a;
    asm("{ .reg .u64 t; cvta.to.shared.u64 t, %1; cvt.u32.u64 %0, t; }" : "=r"(a) : "l"(p));
    return a;
}
__device__ __forceinline__ void ldsm4(uint32_t& r0, uint32_t& r1, uint32_t& r2,
                                      uint32_t& r3, uint32_t addr) {
    asm volatile("ldmatrix.sync.aligned.m8n8.x4.shared.b16 {%0,%1,%2,%3}, [%4];"
                 : "=r"(r0), "=r"(r1), "=r"(r2), "=r"(r3) : "r"(addr));
}
__device__ __forceinline__ void mma_bf16(float* d, const uint32_t* a, const uint32_t* b) {
    asm volatile(
        "mma.sync.aligned.m16n8k16.row.col.f32.bf16.bf16.f32 "
        "{%0,%1,%2,%3}, {%4,%5,%6,%7}, {%8,%9}, {%0,%1,%2,%3};"
        : "+f"(d[0]), "+f"(d[1]), "+f"(d[2]), "+f"(d[3])
        : "r"(a[0]), "r"(a[1]), "r"(a[2]), "r"(a[3]), "r"(b[0]), "r"(b[1]));
}
__device__ __forceinline__ void mma_fp8(float* d, const uint32_t* a, const uint32_t* b) {
    asm volatile(
        "mma.sync.aligned.m16n8k32.row.col.f32.e4m3.e4m3.f32 "
        "{%0,%1,%2,%3}, {%4,%5,%6,%7}, {%8,%9}, {%0,%1,%2,%3};"
        : "+f"(d[0]), "+f"(d[1]), "+f"(d[2]), "+f"(d[3])
        : "r"(a[0]), "r"(a[1]), "r"(a[2]), "r"(a[3]), "r"(b[0]), "r"(b[1]));
}

#define PITCH 72     // bf16 elems per smem row (144 B)
#define PITCHB 144   // bytes per fp8 smem row

// ---------------------------------------------------------------- weights -> fp8 (x64)
__global__ void pack_weights(const float* __restrict__ Wq, const float* __restrict__ bq,
                             const float* __restrict__ Wk, const float* __restrict__ bk,
                             const float* __restrict__ Wv, const float* __restrict__ bv) {
    int i = blockIdx.x, t = threadIdx.x;
    const float* src; float bs;
    if (i < 64) { src = Wq + (size_t)i * NC; bs = bq[i]; }
    else if (i < 128) { src = Wk + (size_t)(i - 64) * NC; bs = bk[i - 64]; }
    else { src = Wv + (size_t)(i - 128) * NC; bs = bv[i - 128]; }
    unsigned char* dst = gW8 + (size_t)i * NC;
    for (int c = t; c < NC; c += 256)
        dst[c] = __nv_cvt_float_to_fp8(src[c] * 64.0f, __NV_SATFINITE, __NV_E4M3);
    if (t == 0) gBiasF[i] = bs;
}

// ---------------------------------------------------------------- x fp32[c,n] -> fp8[n,c]
__global__ void convert_x(const float* __restrict__ x) {
    __shared__ float tile[32][33];
    int tx = threadIdx.x, ty = threadIdx.y;
    int n0 = blockIdx.x << 5, c0 = blockIdx.y << 5, b = blockIdx.z;
#pragma unroll
    for (int j = 0; j < 4; j++)
        tile[ty + 8 * j][tx] = x[((size_t)b * NC + c0 + ty + 8 * j) * NN + n0 + tx];
    __syncthreads();
    int t = ty * 32 + tx;
    int n = t >> 3, c4 = (t & 7) << 2;
    uint32_t pk = 0;
#pragma unroll
    for (int j = 0; j < 4; j++)
        pk |= (uint32_t)__nv_cvt_float_to_fp8(tile[c4 + j][n], __NV_SATFINITE, __NV_E4M3)
              << (8 * j);
    *(uint32_t*)&gX8[((size_t)b * NN + n0 + n) * NC + c0 + c4] = pk;
}

// ---------------------------------------------------------------- fused QKV conv (fp8)
// D[i,n] = sum_c W8[i,c] * X8[n,c] / 64 + bias.  CTA 128x128, K=512 in 4 chunks of 128.
__global__ void conv_mma() {
    __shared__ __align__(16) unsigned char As[128 * PITCHB];
    __shared__ __align__(16) unsigned char Bs[128 * PITCHB];
    __shared__ float sVs[4][128];
    int t = threadIdx.x, wid = t >> 5, lane = t & 31;
    int bi = blockIdx.x << 7, bn = blockIdx.y << 7, b = blockIdx.z;
    int wm = wid & 1, wn = wid >> 1;
    const unsigned char* Ag = gW8 + (size_t)bi * NC;
    const unsigned char* Bg = gX8 + ((size_t)b * NN + bn) * NC;
    float acc[4][4][4] = {};
    uint32_t aBase = smem_to_u32(As), bBase = smem_to_u32(Bs);
    int g = lane >> 3, lr = lane & 7;
    uint32_t aAddr = aBase + (uint32_t)((wm * 64 + (g & 1) * 8 + lr) * PITCHB + (g >> 1) * 16);
    uint32_t bAddr = bBase + (uint32_t)((wn * 32 + (g >> 1) * 8 + lr) * PITCHB + (g & 1) * 16);
    int lrow = t >> 1, lcol = (t & 1) * 64;

    for (int ch = 0; ch < 4; ch++) {
        int kb = ch * 128;
        const uint4* sa = (const uint4*)(Ag + (size_t)lrow * NC + kb + lcol);
        uint4* da = (uint4*)(As + lrow * PITCHB + lcol);
        da[0] = sa[0]; da[1] = sa[1]; da[2] = sa[2]; da[3] = sa[3];
        const uint4* sb = (const uint4*)(Bg + (size_t)lrow * NC + kb + lcol);
        uint4* db = (uint4*)(Bs + lrow * PITCHB + lcol);
        db[0] = sb[0]; db[1] = sb[1]; db[2] = sb[2]; db[3] = sb[3];
        __syncthreads();
#pragma unroll
        for (int ks = 0; ks < 4; ks++) {
            int kkb = ks * 32;  // 32 fp8 per mma step
            uint32_t a[4][4], bf[4][2];
#pragma unroll
            for (int mi = 0; mi < 4; mi++)
                ldsm4(a[mi][0], a[mi][1], a[mi][2], a[mi][3],
                      aAddr + mi * (16 * PITCHB) + kkb);
#pragma unroll
            for (int p = 0; p < 2; p++) {
                uint32_t r0, r1, r2, r3;
                ldsm4(r0, r1, r2, r3, bAddr + p * (16 * PITCHB) + kkb);
                bf[2 * p][0] = r0; bf[2 * p][1] = r1;
                bf[2 * p + 1][0] = r2; bf[2 * p + 1][1] = r3;
            }
#pragma unroll
            for (int mi = 0; mi < 4; mi++)
#pragma unroll
                for (int ni = 0; ni < 4; ni++)
                    mma_fp8(acc[mi][ni], a[mi], bf[ni]);
        }
        __syncthreads();
    }

    const float INV64 = 0.015625f;
    int r = lane >> 2, cp = (lane & 3) << 1;
#pragma unroll
    for (int mi = 0; mi < 4; mi++) {
#pragma unroll
        for (int half = 0; half < 2; half++) {
            int localrow = wm * 64 + mi * 16 + half * 8 + r;
            int ig = bi + localrow;
            float bias = gBiasF[ig];
            __nv_bfloat16* dst;
            if (ig < 64)       dst = gQh + ((size_t)b * NM + ig) * NN;
            else if (ig < 128) dst = gKh + ((size_t)b * NM + ig - 64) * NN;
            else               dst = gVh + ((size_t)b * NC + ig - 128) * NN;
            dst += bn + wn * 32;
            float rowsum = 0.f;
#pragma unroll
            for (int ni = 0; ni < 4; ni++) {
                float vx = acc[mi][ni][half * 2] * INV64 + bias;
                float vy = acc[mi][ni][half * 2 + 1] * INV64 + bias;
                rowsum += vx + vy;
                __nv_bfloat162 v = __floats2bfloat162_rn(vx, vy);
                *(uint32_t*)&dst[ni * 8 + cp] = *(uint32_t*)&v;
            }
            rowsum += __shfl_xor_sync(0xFFFFFFFFu, rowsum, 1);
            rowsum += __shfl_xor_sync(0xFFFFFFFFu, rowsum, 2);
            if ((lane & 3) == 0) sVs[wn][localrow] = rowsum;
        }
    }
    __syncthreads();
    if (t < 128 && bi > 0) {
        float vp = sVs[0][t] + sVs[1][t] + sVs[2][t] + sVs[3][t];
        int c = bi - 128 + t;
        gVsumP[((size_t)blockIdx.y * NB + b) * NC + c] = vp;
    }
}

// ---------------------------------------------------------------- normalize Q,K (+ ksum partials)
__global__ void normalize_qk() {
    __shared__ float Qs[64][33];
    __shared__ float Ks[64][33];
    __shared__ float sKs[8][64];
    int t = threadIdx.x;
    int n0 = blockIdx.x << 5;
    int b = blockIdx.y;
    int row = t >> 2, off = (t & 3) << 3;
    uint4 qv = *(const uint4*)(gQh + ((size_t)b * NM + row) * NN + n0 + off);
    uint4 kv = *(const uint4*)(gKh + ((size_t)b * NM + row) * NN + n0 + off);
    const __nv_bfloat162* qp = (const __nv_bfloat162*)&qv;
    const __nv_bfloat162* kp = (const __nv_bfloat162*)&kv;
#pragma unroll
    for (int j = 0; j < 4; j++) {
        float2 fq = __bfloat1622float2(qp[j]);
        float2 fk = __bfloat1622float2(kp[j]);
        Qs[row][off + 2 * j] = fq.x; Qs[row][off + 2 * j + 1] = fq.y;
        Ks[row][off + 2 * j] = fk.x; Ks[row][off + 2 * j + 1] = fk.y;
    }
    __syncthreads();
    int w = t >> 5, lane = t & 31;
    float kp1 = 0.f, kp2 = 0.f;
#pragma unroll
    for (int j = 0; j < 4; j++) {
        int col = (w << 2) + j;
        float q1 = Qs[lane][col], q2 = Qs[lane + 32][col];
        float k1 = Ks[lane][col], k2 = Ks[lane + 32][col];
        float sq = q1 * q1 + q2 * q2;
        float sk = k1 * k1 + k2 * k2;
#pragma unroll
        for (int o = 16; o; o >>= 1) {
            sq += __shfl_xor_sync(0xFFFFFFFFu, sq, o);
            sk += __shfl_xor_sync(0xFFFFFFFFu, sk, o);
        }
        float rq = rsqrtf(sq + 1e-30f), rk = rsqrtf(sk + 1e-30f);
        __nv_bfloat16* qd = gQnTh + ((size_t)b * NN + n0 + col) * NM;
        qd[lane] = __float2bfloat16(q1 * rq);
        qd[lane + 32] = __float2bfloat16(q2 * rq);
        float kn1 = k1 * rk, kn2 = k2 * rk;
        kp1 += kn1; kp2 += kn2;
        Ks[lane][col] = kn1;
        Ks[lane + 32][col] = kn2;
    }
    sKs[w][lane] = kp1;
    sKs[w][lane + 32] = kp2;
    __syncthreads();
    __nv_bfloat162 o2[4];
#pragma unroll
    for (int j = 0; j < 4; j++)
        o2[j] = __floats2bfloat162_rn(Ks[row][off + 2 * j], Ks[row][off + 2 * j + 1]);
    *(uint4*)(gKnH + ((size_t)b * NM + row) * NN + n0 + off) = *(uint4*)o2;
    if (t < 64) {
        float s = 0.f;
#pragma unroll
        for (int ww = 0; ww < 8; ww++) s += sKs[ww][t];
        gKsumP[((size_t)blockIdx.x * NB + b) * NM + t] = s;
    }
}

// ---------------------------------------------------------------- KV contraction (bf16)
__global__ void kv_mma() {
    __shared__ __align__(16) __nv_bfloat16 As[128][PITCH];
    __shared__ __align__(16) __nv_bfloat16 Bs[64][PITCH];
    int t = threadIdx.x, wid = t >> 5, lane = t & 31;
    int bc = blockIdx.x << 7, split = blockIdx.y, b = blockIdx.z;
    int wm = wid & 3, wn = wid >> 2;
    const __nv_bfloat16* Ag = gVh + ((size_t)b * NC + bc) * NN + split * 512;
    const __nv_bfloat16* Bg = gKnH + (size_t)b * NM * NN + split * 512;
    float acc[2][4][4] = {};
    uint32_t aBase = smem_to_u32(As), bBase = smem_to_u32(Bs);
    int g = lane >> 3, lr = lane & 7;
    uint32_t aAddr = aBase + (uint32_t)(((wm * 32 + (g & 1) * 8 + lr) * PITCH + (g >> 1) * 8) * 2);
    uint32_t bAddr = bBase + (uint32_t)(((wn * 32 + (g >> 1) * 8 + lr) * PITCH + (g & 1) * 8) * 2);
    int arow = t >> 1, acol = (t & 1) * 32;
    int brow = t >> 2, bcol = (t & 3) * 16;

    for (int ch = 0; ch < 8; ch++) {
        int k0 = ch * 64;
        const uint4* sa = (const uint4*)(Ag + (size_t)arow * NN + k0 + acol);
        uint4* da = (uint4*)(&As[arow][acol]);
        da[0] = sa[0]; da[1] = sa[1]; da[2] = sa[2]; da[3] = sa[3];
        const uint4* sb = (const uint4*)(Bg + (size_t)brow * NN + k0 + bcol);
        uint4* db = (uint4*)(&Bs[brow][bcol]);
        db[0] = sb[0]; db[1] = sb[1];
        __syncthreads();
#pragma unroll
        for (int ks = 0; ks < 4; ks++) {
            int kk = ks * 32;
            uint32_t a[2][4], bf[4][2];
#pragma unroll
            for (int mi = 0; mi < 2; mi++)
                ldsm4(a[mi][0], a[mi][1], a[mi][2], a[mi][3],
                      aAddr + mi * (16 * PITCH * 2) + kk);
#pragma unroll
            for (int p = 0; p < 2; p++) {
                uint32_t r0, r1, r2, r3;
                ldsm4(r0, r1, r2, r3, bAddr + p * (16 * PITCH * 2) + kk);
                bf[2 * p][0] = r0; bf[2 * p][1] = r1;
                bf[2 * p + 1][0] = r2; bf[2 * p + 1][1] = r3;
            }
#pragma unroll
            for (int mi = 0; mi < 2; mi++)
#pragma unroll
                for (int ni = 0; ni < 4; ni++)
                    mma_bf16(acc[mi][ni], a[mi], bf[ni]);
        }
        __syncthreads();
    }

    int r = lane >> 2, cp = (lane & 3) << 1;
#pragma unroll
    for (int mi = 0; mi < 2; mi++) {
#pragma unroll
        for (int half = 0; half < 2; half++) {
            int c = bc + wm * 32 + mi * 16 + half * 8 + r;
            float* dst = gMatPartT + (((size_t)split * NB + b) * NC + c) * NM + wn * 32;
#pragma unroll
            for (int ni = 0; ni < 4; ni++) {
                float2 v = make_float2(acc[mi][ni][half * 2], acc[mi][ni][half * 2 + 1]);
                *(float2*)&dst[ni * 8 + cp] = v;
            }
        }
    }
}

// ---------------------------------------------------------------- one combined reduction
__global__ void reduce_all() {
    int idx = blockIdx.x * 256 + threadIdx.x;
    const int NMAT = NB * NC * NM;            // 262144
    const int NVS = NB * NC;                  // 4096
    if (idx < NMAT) {
        float s = 0.f;
#pragma unroll
        for (int sp = 0; sp < NSPLIT; sp++)
            s += gMatPartT[(size_t)sp * NMAT + idx];
        gMatTh[idx] = __float2bfloat16(s);
    } else if (idx < NMAT + NVS) {
        int i = idx - NMAT;
        int b = i >> 9, c = i & 511;
        float s = 0.f;
#pragma unroll
        for (int blk = 0; blk < 32; blk++)
            s += gVsumP[((size_t)blk * NB + b) * NC + c];
        gVsum[b * NC + c] = s;
    } else if (idx < NMAT + NVS + NB * NM) {
        int i = idx - NMAT - NVS;
        int b = i >> 6, m = i & 63;
        float s = 0.f;
        for (int blk = 0; blk < 128; blk++)
            s += gKsumP[((size_t)blk * NB + b) * NM + m];
        gKsum[b * NM + m] = s;
    }
}

// ---------------------------------------------------------------- final GEMM + tailor + epilogue
__global__ void final_mma(const float* __restrict__ x, const float* __restrict__ gamma,
                          float* __restrict__ out) {
    __shared__ __align__(16) __nv_bfloat16 As[128][PITCH];
    __shared__ __align__(16) __nv_bfloat16 Bs[128][PITCH];
    __shared__ float ksS[64];
    __shared__ float tailorS[128];
    int t = threadIdx.x, wid = t >> 5, lane = t & 31;
    int bc = blockIdx.x << 7, bn = blockIdx.y << 7, b = blockIdx.z;
    int wm = wid & 1, wn = wid >> 1;
    const __nv_bfloat16* Ag = gMatTh + ((size_t)b * NC + bc) * NM;
    const __nv_bfloat16* Bg = gQnTh + ((size_t)b * NN + bn) * NM;
    float acc[4][4][4] = {};
    uint32_t aBase = smem_to_u32(As), bBase = smem_to_u32(Bs);
    int g = lane >> 3, lr = lane & 7;
    uint32_t aAddr = aBase + (uint32_t)(((wm * 64 + (g & 1) * 8 + lr) * PITCH + (g >> 1) * 8) * 2);
    uint32_t bAddr = bBase + (uint32_t)(((wn * 32 + (g >> 1) * 8 + lr) * PITCH + (g & 1) * 8) * 2);
    {
        int row = t >> 1, col = (t & 1) * 32;
        const uint4* sa = (const uint4*)(Ag + (size_t)row * NM + col);
        uint4* da = (uint4*)(&As[row][col]);
        da[0] = sa[0]; da[1] = sa[1]; da[2] = sa[2]; da[3] = sa[3];
        const uint4* sb = (const uint4*)(Bg + (size_t)row * NM + col);
        uint4* db = (uint4*)(&Bs[row][col]);
        db[0] = sb[0]; db[1] = sb[1]; db[2] = sb[2]; db[3] = sb[3];
    }
    if (t < 64) ksS[t] = gKsum[b * NM + t] + EPSF;
    __syncthreads();
    if (t < 128) {
        const __nv_bfloat162* qr = (const __nv_bfloat162*)&Bs[t][0];
        float s = 0.f;
#pragma unroll
        for (int mm = 0; mm < 32; mm++) {
            float2 f = __bfloat1622float2(qr[mm]);
            s += f.x * ksS[2 * mm] + f.y * ksS[2 * mm + 1];
        }
        tailorS[t] = 1.0f / ((float)NN + s);
    }
    __syncthreads();
#pragma unroll
    for (int ks = 0; ks < 4; ks++) {
        int kk = ks * 32;
        uint32_t a[4][4], bf[4][2];
#pragma unroll
        for (int mi = 0; mi < 4; mi++)
            ldsm4(a[mi][0], a[mi][1], a[mi][2], a[mi][3],
                  aAddr + mi * (16 * PITCH * 2) + kk);
#pragma unroll
        for (int p = 0; p < 2; p++) {
            uint32_t r0, r1, r2, r3;
            ldsm4(r0, r1, r2, r3, bAddr + p * (16 * PITCH * 2) + kk);
            bf[2 * p][0] = r0; bf[2 * p][1] = r1;
            bf[2 * p + 1][0] = r2; bf[2 * p + 1][1] = r3;
        }
#pragma unroll
        for (int mi = 0; mi < 4; mi++)
#pragma unroll
            for (int ni = 0; ni < 4; ni++)
                mma_bf16(acc[mi][ni], a[mi], bf[ni]);
    }

    int r = lane >> 2, cp = (lane & 3) << 1;
    float gm = gamma[0];
#pragma unroll
    for (int mi = 0; mi < 4; mi++) {
#pragma unroll
        for (int half = 0; half < 2; half++) {
            int c = bc + wm * 64 + mi * 16 + half * 8 + r;
            float vs = gVsum[b * NC + c];
            const float* xr = x + ((size_t)b * NC + c) * NN + bn + wn * 32;
            float* orow = out + ((size_t)b * NC + c) * NN + bn + wn * 32;
#pragma unroll
            for (int ni = 0; ni < 4; ni++) {
                int n = ni * 8 + cp;
                float2 xv = *(const float2*)&xr[n];
                float tv0 = tailorS[wn * 32 + n];
                float tv1 = tailorS[wn * 32 + n + 1];
                float2 ov;
                ov.x = xv.x + gm * (vs + acc[mi][ni][half * 2]) * tv0;
                ov.y = xv.y + gm * (vs + acc[mi][ni][half * 2 + 1]) * tv1;
                *(float2*)&orow[n] = ov;
            }
        }
    }
}

// ---------------------------------------------------------------- launch
extern "C" void kernel_launch(void* const* d_in, const int* in_sizes, int n_in,
                              void* d_out, int out_size) {
    const float* x = (const float*)d_in[0];
    const float* Wq = (const float*)d_in[1];
    const float* bq = (const float*)d_in[2];
    const float* Wk = (const float*)d_in[3];
    const float* bk = (const float*)d_in[4];
    const float* Wv = (const float*)d_in[5];
    const float* bv = (const float*)d_in[6];
    const float* gamma = (const float*)d_in[7];
    float* out = (float*)d_out;
    (void)in_sizes; (void)n_in; (void)out_size;

    pack_weights<<<NI, 256>>>(Wq, bq, Wk, bk, Wv, bv);
    convert_x<<<dim3(NN / 32, NC / 32, NB), dim3(32, 8)>>>(x);
    conv_mma<<<dim3(NI / 128, NN / 128, NB), 256>>>();
    normalize_qk<<<dim3(NN / 32, NB), 256>>>();
    kv_mma<<<dim3(NC / 128, NSPLIT, NB), 256>>>();
    reduce_all<<<(NB * NC * NM + NB * NC + NB * NM + 255) / 256, 256>>>();
    final_mma<<<dim3(NC / 128, NN / 128, NB), 256>>>(x, gamma, out);
}

// round 6
// speedup vs baseline: 5.4862x; 1.0637x over previous
#include <cuda_runtime.h>
#include <cuda_bf16.h>
#include <cuda_fp8.h>
#include <cstdint>

#define NB 8
#define NC 512
#define NM 64
#define NN 4096
#define NI 640
#define EPSF 1e-6f
#define NSPLIT 8

// ---------------------------------------------------------------- scratch
__device__ __align__(16) unsigned char gW8[NI * NC];
__device__ float gBiasF[NI];
__device__ __align__(16) unsigned char gX8[(size_t)NB * NN * NC];    // fp8 x, [b,n,c]
__device__ __align__(16) __nv_bfloat16 gVh[(size_t)NB * NC * NN];    // [b,c,n]
__device__ __align__(16) __nv_bfloat16 gQnTh[(size_t)NB * NN * NM];  // [b,n,m]
__device__ __align__(16) __nv_bfloat16 gKnH[(size_t)NB * NM * NN];   // [b,m,n]
__device__ __align__(16) float gMatPartT[(size_t)NSPLIT * NB * NC * NM];
__device__ __align__(16) __nv_bfloat16 gMatTh[(size_t)NB * NC * NM]; // [b,c,m]
__device__ float gVsumP[(size_t)32 * NB * NC];   // [nblk,b,c]
__device__ float gKsumP[(size_t)32 * NB * NM];   // [nblk,b,m]
__device__ float gKsum[NB * NM];
__device__ float gVsum[NB * NC];

// ---------------------------------------------------------------- helpers
__device__ __forceinline__ uint32_t smem_to_u32(const void* p) {
    uint32_t a;
    asm("{ .reg .u64 t; cvta.to.shared.u64 t, %1; cvt.u32.u64 %0, t; }" : "=r"(a) : "l"(p));
    return a;
}
__device__ __forceinline__ void ldsm4(uint32_t& r0, uint32_t& r1, uint32_t& r2,
                                      uint32_t& r3, uint32_t addr) {
    asm volatile("ldmatrix.sync.aligned.m8n8.x4.shared.b16 {%0,%1,%2,%3}, [%4];"
                 : "=r"(r0), "=r"(r1), "=r"(r2), "=r"(r3) : "r"(addr));
}
__device__ __forceinline__ void mma_bf16(float* d, const uint32_t* a, const uint32_t* b) {
    asm volatile(
        "mma.sync.aligned.m16n8k16.row.col.f32.bf16.bf16.f32 "
        "{%0,%1,%2,%3}, {%4,%5,%6,%7}, {%8,%9}, {%0,%1,%2,%3};"
        : "+f"(d[0]), "+f"(d[1]), "+f"(d[2]), "+f"(d[3])
        : "r"(a[0]), "r"(a[1]), "r"(a[2]), "r"(a[3]), "r"(b[0]), "r"(b[1]));
}
__device__ __forceinline__ void mma_fp8(float* d, const uint32_t* a, const uint32_t* b) {
    asm volatile(
        "mma.sync.aligned.m16n8k32.row.col.f32.e4m3.e4m3.f32 "
        "{%0,%1,%2,%3}, {%4,%5,%6,%7}, {%8,%9}, {%0,%1,%2,%3};"
        : "+f"(d[0]), "+f"(d[1]), "+f"(d[2]), "+f"(d[3])
        : "r"(a[0]), "r"(a[1]), "r"(a[2]), "r"(a[3]), "r"(b[0]), "r"(b[1]));
}
__device__ __forceinline__ void cp_async16(uint32_t dst, const void* src) {
    asm volatile("cp.async.cg.shared.global [%0], [%1], 16;" :: "r"(dst), "l"(src));
}
#define CP_COMMIT() asm volatile("cp.async.commit_group;" ::: "memory")
#define CP_WAIT1() asm volatile("cp.async.wait_group 1;" ::: "memory")
#define CP_WAIT0() asm volatile("cp.async.wait_group 0;" ::: "memory")

#define PITCH 72     // bf16 elems per smem row (144 B)
#define PITCHB 144   // bytes per fp8 smem row
#define QKPITCH 130  // bf16 pitch for epilogue QK tile

// ---------------------------------------------------------------- weights -> fp8 (x64)
__global__ void pack_weights(const float* __restrict__ Wq, const float* __restrict__ bq,
                             const float* __restrict__ Wk, const float* __restrict__ bk,
                             const float* __restrict__ Wv, const float* __restrict__ bv) {
    int i = blockIdx.x, t = threadIdx.x;
    const float* src; float bs;
    if (i < 64) { src = Wq + (size_t)i * NC; bs = bq[i]; }
    else if (i < 128) { src = Wk + (size_t)(i - 64) * NC; bs = bk[i - 64]; }
    else { src = Wv + (size_t)(i - 128) * NC; bs = bv[i - 128]; }
    unsigned char* dst = gW8 + (size_t)i * NC;
    for (int c = t; c < NC; c += 256)
        dst[c] = __nv_cvt_float_to_fp8(src[c] * 64.0f, __NV_SATFINITE, __NV_E4M3);
    if (t == 0) gBiasF[i] = bs;
}

// ---------------------------------------------------------------- x fp32[c,n] -> fp8[n,c]
__global__ void convert_x(const float* __restrict__ x) {
    __shared__ float tile[32][33];
    int tx = threadIdx.x, ty = threadIdx.y;
    int n0 = blockIdx.x << 5, c0 = blockIdx.y << 5, b = blockIdx.z;
#pragma unroll
    for (int j = 0; j < 4; j++)
        tile[ty + 8 * j][tx] = x[((size_t)b * NC + c0 + ty + 8 * j) * NN + n0 + tx];
    __syncthreads();
    int t = ty * 32 + tx;
    int n = t >> 3, c4 = (t & 7) << 2;
    uint32_t pk = 0;
#pragma unroll
    for (int j = 0; j < 4; j++)
        pk |= (uint32_t)__nv_cvt_float_to_fp8(tile[c4 + j][n], __NV_SATFINITE, __NV_E4M3)
              << (8 * j);
    *(uint32_t*)&gX8[((size_t)b * NN + n0 + n) * NC + c0 + c4] = pk;
}

// ---------------------------------------------------------------- fused QKV conv (fp8, cp.async)
// D[i,n] = sum_c W8[i,c]*X8[n,c]/64 + bias.  CTA 128x128, K=512 in 4 chunks of 128.
// bi==0 block: epilogue fuses Q/K L2-normalization (+ ksum partials).
// bi>=1 blocks: write V bf16 (+ vsum partials).
#define STAGEB 36864
__global__ void conv_mma() {
    extern __shared__ __align__(16) unsigned char dsm[];
    __shared__ float sVs[4][128];
    uint32_t base = smem_to_u32(dsm);
    int t = threadIdx.x, wid = t >> 5, lane = t & 31;
    int bi = blockIdx.x << 7, bn = blockIdx.y << 7, b = blockIdx.z;
    int wm = wid & 1, wn = wid >> 1;
    const unsigned char* Ag = gW8 + (size_t)bi * NC;
    const unsigned char* Bg = gX8 + ((size_t)b * NN + bn) * NC;
    float acc[4][4][4] = {};
    int g = lane >> 3, lr = lane & 7;
    uint32_t aOff = (uint32_t)((wm * 64 + (g & 1) * 8 + lr) * PITCHB + (g >> 1) * 16);
    uint32_t bOff = 18432u + (uint32_t)((wn * 32 + (g >> 1) * 8 + lr) * PITCHB + (g & 1) * 16);
    int lrow = t >> 1, lcol = (t & 1) * 64;

    // prefetch chunk 0
    {
        const unsigned char* a = Ag + (size_t)lrow * NC + lcol;
        uint32_t da = base + (uint32_t)(lrow * PITCHB + lcol);
        cp_async16(da, a); cp_async16(da + 16, a + 16);
        cp_async16(da + 32, a + 32); cp_async16(da + 48, a + 48);
        const unsigned char* bb = Bg + (size_t)lrow * NC + lcol;
        uint32_t db = base + 18432u + (uint32_t)(lrow * PITCHB + lcol);
        cp_async16(db, bb); cp_async16(db + 16, bb + 16);
        cp_async16(db + 32, bb + 32); cp_async16(db + 48, bb + 48);
        CP_COMMIT();
    }

    for (int ch = 0; ch < 4; ch++) {
        if (ch < 3) {
            int kb = (ch + 1) * 128;
            uint32_t s = (uint32_t)(((ch + 1) & 1) * STAGEB);
            const unsigned char* a = Ag + (size_t)lrow * NC + kb + lcol;
            uint32_t da = base + s + (uint32_t)(lrow * PITCHB + lcol);
            cp_async16(da, a); cp_async16(da + 16, a + 16);
            cp_async16(da + 32, a + 32); cp_async16(da + 48, a + 48);
            const unsigned char* bb = Bg + (size_t)lrow * NC + kb + lcol;
            uint32_t db = base + s + 18432u + (uint32_t)(lrow * PITCHB + lcol);
            cp_async16(db, bb); cp_async16(db + 16, bb + 16);
            cp_async16(db + 32, bb + 32); cp_async16(db + 48, bb + 48);
            CP_COMMIT();
            CP_WAIT1();
        } else {
            CP_WAIT0();
        }
        __syncthreads();
        uint32_t stg = base + (uint32_t)((ch & 1) * STAGEB);
#pragma unroll
        for (int ks = 0; ks < 4; ks++) {
            int kkb = ks * 32;
            uint32_t a[4][4], bf[4][2];
#pragma unroll
            for (int mi = 0; mi < 4; mi++)
                ldsm4(a[mi][0], a[mi][1], a[mi][2], a[mi][3],
                      stg + aOff + mi * (16 * PITCHB) + kkb);
#pragma unroll
            for (int p = 0; p < 2; p++) {
                uint32_t r0, r1, r2, r3;
                ldsm4(r0, r1, r2, r3, stg + bOff + p * (16 * PITCHB) + kkb);
                bf[2 * p][0] = r0; bf[2 * p][1] = r1;
                bf[2 * p + 1][0] = r2; bf[2 * p + 1][1] = r3;
            }
#pragma unroll
            for (int mi = 0; mi < 4; mi++)
#pragma unroll
                for (int ni = 0; ni < 4; ni++)
                    mma_fp8(acc[mi][ni], a[mi], bf[ni]);
        }
        __syncthreads();
    }

    const float INV64 = 0.015625f;
    int r = lane >> 2, cp = (lane & 3) << 1;

    if (bi == 0) {
        // -------- fused Q/K normalize epilogue --------
        __nv_bfloat16* sQK = (__nv_bfloat16*)dsm;  // [128][QKPITCH], aliases stage0
#pragma unroll
        for (int mi = 0; mi < 4; mi++) {
#pragma unroll
            for (int half = 0; half < 2; half++) {
                int localrow = wm * 64 + mi * 16 + half * 8 + r;
                float bias = gBiasF[localrow];
#pragma unroll
                for (int ni = 0; ni < 4; ni++) {
                    float vx = acc[mi][ni][half * 2] * INV64 + bias;
                    float vy = acc[mi][ni][half * 2 + 1] * INV64 + bias;
                    __nv_bfloat162 v = __floats2bfloat162_rn(vx, vy);
                    *(uint32_t*)&sQK[localrow * QKPITCH + wn * 32 + ni * 8 + cp] =
                        *(uint32_t*)&v;
                }
            }
        }
        __syncthreads();
        int c = t & 127, part = t >> 7;
        if (part == 0) {
            // Q: rows 0..63, write transposed gQnTh[b, bn+c, :]
            float sq = 0.f;
#pragma unroll
            for (int m = 0; m < 64; m++) {
                float v = __bfloat162float(sQK[m * QKPITCH + c]);
                sq += v * v;
            }
            float rq = rsqrtf(sq + 1e-30f);
            __nv_bfloat16 tmp[64];
#pragma unroll
            for (int m = 0; m < 64; m++)
                tmp[m] = __float2bfloat16(__bfloat162float(sQK[m * QKPITCH + c]) * rq);
            uint4* dst = (uint4*)(gQnTh + ((size_t)b * NN + bn + c) * NM);
            const uint4* srcv = (const uint4*)tmp;
#pragma unroll
            for (int q8 = 0; q8 < 8; q8++) dst[q8] = srcv[q8];
        } else {
            // K: rows 64..127, write row-major gKnH[b, m, bn+c] + normalized back to smem
            float sk = 0.f;
#pragma unroll
            for (int m = 0; m < 64; m++) {
                float v = __bfloat162float(sQK[(64 + m) * QKPITCH + c]);
                sk += v * v;
            }
            float rk = rsqrtf(sk + 1e-30f);
#pragma unroll
            for (int m = 0; m < 64; m++) {
                float v = __bfloat162float(sQK[(64 + m) * QKPITCH + c]);
                __nv_bfloat16 kn = __float2bfloat16(v * rk);
                sQK[(64 + m) * QKPITCH + c] = kn;
                gKnH[((size_t)b * NM + m) * NN + bn + c] = kn;
            }
        }
        __syncthreads();
        // ksum partials from normalized K in smem
        int m = t >> 2, q = t & 3;
        float s = 0.f;
#pragma unroll
        for (int cc = 0; cc < 32; cc++)
            s += __bfloat162float(sQK[(64 + m) * QKPITCH + q * 32 + cc]);
        s += __shfl_xor_sync(0xFFFFFFFFu, s, 1);
        s += __shfl_xor_sync(0xFFFFFFFFu, s, 2);
        if (q == 0) gKsumP[((size_t)blockIdx.y * NB + b) * NM + m] = s;
    } else {
        // -------- V epilogue --------
#pragma unroll
        for (int mi = 0; mi < 4; mi++) {
#pragma unroll
            for (int half = 0; half < 2; half++) {
                int localrow = wm * 64 + mi * 16 + half * 8 + r;
                int ig = bi + localrow;
                float bias = gBiasF[ig];
                __nv_bfloat16* dst = gVh + ((size_t)b * NC + ig - 128) * NN + bn + wn * 32;
                float rowsum = 0.f;
#pragma unroll
                for (int ni = 0; ni < 4; ni++) {
                    float vx = acc[mi][ni][half * 2] * INV64 + bias;
                    float vy = acc[mi][ni][half * 2 + 1] * INV64 + bias;
                    rowsum += vx + vy;
                    __nv_bfloat162 v = __floats2bfloat162_rn(vx, vy);
                    *(uint32_t*)&dst[ni * 8 + cp] = *(uint32_t*)&v;
                }
                rowsum += __shfl_xor_sync(0xFFFFFFFFu, rowsum, 1);
                rowsum += __shfl_xor_sync(0xFFFFFFFFu, rowsum, 2);
                if ((lane & 3) == 0) sVs[wn][localrow] = rowsum;
            }
        }
        __syncthreads();
        if (t < 128) {
            float vp = sVs[0][t] + sVs[1][t] + sVs[2][t] + sVs[3][t];
            int c = bi - 128 + t;
            gVsumP[((size_t)blockIdx.y * NB + b) * NC + c] = vp;
        }
    }
}

// ---------------------------------------------------------------- KV contraction (bf16)
__global__ void kv_mma() {
    __shared__ __align__(16) __nv_bfloat16 As[128][PITCH];
    __shared__ __align__(16) __nv_bfloat16 Bs[64][PITCH];
    int t = threadIdx.x, wid = t >> 5, lane = t & 31;
    int bc = blockIdx.x << 7, split = blockIdx.y, b = blockIdx.z;
    int wm = wid & 3, wn = wid >> 2;
    const __nv_bfloat16* Ag = gVh + ((size_t)b * NC + bc) * NN + split * 512;
    const __nv_bfloat16* Bg = gKnH + (size_t)b * NM * NN + split * 512;
    float acc[2][4][4] = {};
    uint32_t aBase = smem_to_u32(As), bBase = smem_to_u32(Bs);
    int g = lane >> 3, lr = lane & 7;
    uint32_t aAddr = aBase + (uint32_t)(((wm * 32 + (g & 1) * 8 + lr) * PITCH + (g >> 1) * 8) * 2);
    uint32_t bAddr = bBase + (uint32_t)(((wn * 32 + (g >> 1) * 8 + lr) * PITCH + (g & 1) * 8) * 2);
    int arow = t >> 1, acol = (t & 1) * 32;
    int brow = t >> 2, bcol = (t & 3) * 16;

    for (int ch = 0; ch < 8; ch++) {
        int k0 = ch * 64;
        const uint4* sa = (const uint4*)(Ag + (size_t)arow * NN + k0 + acol);
        uint4* da = (uint4*)(&As[arow][acol]);
        da[0] = sa[0]; da[1] = sa[1]; da[2] = sa[2]; da[3] = sa[3];
        const uint4* sb = (const uint4*)(Bg + (size_t)brow * NN + k0 + bcol);
        uint4* db = (uint4*)(&Bs[brow][bcol]);
        db[0] = sb[0]; db[1] = sb[1];
        __syncthreads();
#pragma unroll
        for (int ks = 0; ks < 4; ks++) {
            int kk = ks * 32;
            uint32_t a[2][4], bf[4][2];
#pragma unroll
            for (int mi = 0; mi < 2; mi++)
                ldsm4(a[mi][0], a[mi][1], a[mi][2], a[mi][3],
                      aAddr + mi * (16 * PITCH * 2) + kk);
#pragma unroll
            for (int p = 0; p < 2; p++) {
                uint32_t r0, r1, r2, r3;
                ldsm4(r0, r1, r2, r3, bAddr + p * (16 * PITCH * 2) + kk);
                bf[2 * p][0] = r0; bf[2 * p][1] = r1;
                bf[2 * p + 1][0] = r2; bf[2 * p + 1][1] = r3;
            }
#pragma unroll
            for (int mi = 0; mi < 2; mi++)
#pragma unroll
                for (int ni = 0; ni < 4; ni++)
                    mma_bf16(acc[mi][ni], a[mi], bf[ni]);
        }
        __syncthreads();
    }

    int r = lane >> 2, cp = (lane & 3) << 1;
#pragma unroll
    for (int mi = 0; mi < 2; mi++) {
#pragma unroll
        for (int half = 0; half < 2; half++) {
            int c = bc + wm * 32 + mi * 16 + half * 8 + r;
            float* dst = gMatPartT + (((size_t)split * NB + b) * NC + c) * NM + wn * 32;
#pragma unroll
            for (int ni = 0; ni < 4; ni++) {
                float2 v = make_float2(acc[mi][ni][half * 2], acc[mi][ni][half * 2 + 1]);
                *(float2*)&dst[ni * 8 + cp] = v;
            }
        }
    }
}

// ---------------------------------------------------------------- combined reductions
__global__ void reduce_all() {
    int idx = blockIdx.x * 256 + threadIdx.x;
    const int NMAT = NB * NC * NM;
    const int NVS = NB * NC;
    if (idx < NMAT) {
        float s = 0.f;
#pragma unroll
        for (int sp = 0; sp < NSPLIT; sp++)
            s += gMatPartT[(size_t)sp * NMAT + idx];
        gMatTh[idx] = __float2bfloat16(s);
    } else if (idx < NMAT + NVS) {
        int i = idx - NMAT;
        int b = i >> 9, c = i & 511;
        float s = 0.f;
#pragma unroll
        for (int blk = 0; blk < 32; blk++)
            s += gVsumP[((size_t)blk * NB + b) * NC + c];
        gVsum[b * NC + c] = s;
    } else if (idx < NMAT + NVS + NB * NM) {
        int i = idx - NMAT - NVS;
        int b = i >> 6, m = i & 63;
        float s = 0.f;
#pragma unroll
        for (int blk = 0; blk < 32; blk++)
            s += gKsumP[((size_t)blk * NB + b) * NM + m];
        gKsum[b * NM + m] = s;
    }
}

// ---------------------------------------------------------------- final GEMM + tailor + epilogue
__global__ void final_mma(const float* __restrict__ x, const float* __restrict__ gamma,
                          float* __restrict__ out) {
    __shared__ __align__(16) __nv_bfloat16 As[128][PITCH];
    __shared__ __align__(16) __nv_bfloat16 Bs[128][PITCH];
    __shared__ float ksS[64];
    __shared__ float tailorS[128];
    int t = threadIdx.x, wid = t >> 5, lane = t & 31;
    int bc = blockIdx.x << 7, bn = blockIdx.y << 7, b = blockIdx.z;
    int wm = wid & 1, wn = wid >> 1;
    const __nv_bfloat16* Ag = gMatTh + ((size_t)b * NC + bc) * NM;
    const __nv_bfloat16* Bg = gQnTh + ((size_t)b * NN + bn) * NM;
    float acc[4][4][4] = {};
    uint32_t aBase = smem_to_u32(As), bBase = smem_to_u32(Bs);
    int g = lane >> 3, lr = lane & 7;
    uint32_t aAddr = aBase + (uint32_t)(((wm * 64 + (g & 1) * 8 + lr) * PITCH + (g >> 1) * 8) * 2);
    uint32_t bAddr = bBase + (uint32_t)(((wn * 32 + (g >> 1) * 8 + lr) * PITCH + (g & 1) * 8) * 2);
    {
        int row = t >> 1, col = (t & 1) * 32;
        const uint4* sa = (const uint4*)(Ag + (size_t)row * NM + col);
        uint4* da = (uint4*)(&As[row][col]);
        da[0] = sa[0]; da[1] = sa[1]; da[2] = sa[2]; da[3] = sa[3];
        const uint4* sb = (const uint4*)(Bg + (size_t)row * NM + col);
        uint4* db = (uint4*)(&Bs[row][col]);
        db[0] = sb[0]; db[1] = sb[1]; db[2] = sb[2]; db[3] = sb[3];
    }
    if (t < 64) ksS[t] = gKsum[b * NM + t] + EPSF;
    __syncthreads();
    if (t < 128) {
        const __nv_bfloat162* qr = (const __nv_bfloat162*)&Bs[t][0];
        float s = 0.f;
#pragma unroll
        for (int mm = 0; mm < 32; mm++) {
            float2 f = __bfloat1622float2(qr[mm]);
            s += f.x * ksS[2 * mm] + f.y * ksS[2 * mm + 1];
        }
        tailorS[t] = 1.0f / ((float)NN + s);
    }
    __syncthreads();
#pragma unroll
    for (int ks = 0; ks < 4; ks++) {
        int kk = ks * 32;
        uint32_t a[4][4], bf[4][2];
#pragma unroll
        for (int mi = 0; mi < 4; mi++)
            ldsm4(a[mi][0], a[mi][1], a[mi][2], a[mi][3],
                  aAddr + mi * (16 * PITCH * 2) + kk);
#pragma unroll
        for (int p = 0; p < 2; p++) {
            uint32_t r0, r1, r2, r3;
            ldsm4(r0, r1, r2, r3, bAddr + p * (16 * PITCH * 2) + kk);
            bf[2 * p][0] = r0; bf[2 * p][1] = r1;
            bf[2 * p + 1][0] = r2; bf[2 * p + 1][1] = r3;
        }
#pragma unroll
        for (int mi = 0; mi < 4; mi++)
#pragma unroll
            for (int ni = 0; ni < 4; ni++)
                mma_bf16(acc[mi][ni], a[mi], bf[ni]);
    }

    int r = lane >> 2, cp = (lane & 3) << 1;
    float gm = gamma[0];
#pragma unroll
    for (int mi = 0; mi < 4; mi++) {
#pragma unroll
        for (int half = 0; half < 2; half++) {
            int c = bc + wm * 64 + mi * 16 + half * 8 + r;
            float vs = gVsum[b * NC + c];
            const float* xr = x + ((size_t)b * NC + c) * NN + bn + wn * 32;
            float* orow = out + ((size_t)b * NC + c) * NN + bn + wn * 32;
#pragma unroll
            for (int ni = 0; ni < 4; ni++) {
                int n = ni * 8 + cp;
                float2 xv = *(const float2*)&xr[n];
                float tv0 = tailorS[wn * 32 + n];
                float tv1 = tailorS[wn * 32 + n + 1];
                float2 ov;
                ov.x = xv.x + gm * (vs + acc[mi][ni][half * 2]) * tv0;
                ov.y = xv.y + gm * (vs + acc[mi][ni][half * 2 + 1]) * tv1;
                *(float2*)&orow[n] = ov;
            }
        }
    }
}

// ---------------------------------------------------------------- launch
extern "C" void kernel_launch(void* const* d_in, const int* in_sizes, int n_in,
                              void* d_out, int out_size) {
    const float* x = (const float*)d_in[0];
    const float* Wq = (const float*)d_in[1];
    const float* bq = (const float*)d_in[2];
    const float* Wk = (const float*)d_in[3];
    const float* bk = (const float*)d_in[4];
    const float* Wv = (const float*)d_in[5];
    const float* bv = (const float*)d_in[6];
    const float* gamma = (const float*)d_in[7];
    float* out = (float*)d_out;
    (void)in_sizes; (void)n_in; (void)out_size;

    cudaFuncSetAttribute(conv_mma, cudaFuncAttributeMaxDynamicSharedMemorySize, 2 * STAGEB);

    pack_weights<<<NI, 256>>>(Wq, bq, Wk, bk, Wv, bv);
    convert_x<<<dim3(NN / 32, NC / 32, NB), dim3(32, 8)>>>(x);
    conv_mma<<<dim3(NI / 128, NN / 128, NB), 256, 2 * STAGEB>>>();
    kv_mma<<<dim3(NC / 128, NSPLIT, NB), 256>>>();
    reduce_all<<<(NB * NC * NM + NB * NC + NB * NM + 255) / 256, 256>>>();
    final_mma<<<dim3(NC / 128, NN / 128, NB), 256>>>(x, gamma, out);
}